// round 12
// baseline (speedup 1.0000x reference)
#include <cuda_runtime.h>
#include <cuda_bf16.h>
#include <stdint.h>

// Periodic radius-graph: B=4, N=512, K=27.
// Outputs concatenated in d_out (float32):
//   [0,      S)   distances   [B,N,N,K]
//   [S,     4S)   distance_vec[B,N,N,K,3]
//   [4S,    5S)   mask        [B,N,N,K]  (0.0/1.0)
//   [5S, 5S+81B)  offset_cart [B,27,3]
// with S = B*N*N*K.
//
// ALL outputs staged in smem and drained as linear cp.async.bulk
// shared->global bursts (dist 3072 B, mask 3072 B, vec 9216 B per chunk),
// double-buffered, so DRAM sees only large sequential TMA writes.

#define KIMG   27
#define MAXN   512
#define TPB    256
#define CH     768                 // elems/chunk = 3 per thread; NK/CH = 18
#define NCHUNK (MAXN * KIMG / CH)  // 18
// TPB mod KIMG: 256 = 9*27 + 13
#define JSTEP  9
#define KSTEP  13

__device__ __forceinline__ void bulk_s2g(void* gdst, uint32_t ssrc, uint32_t bytes) {
    asm volatile(
        "cp.async.bulk.global.shared::cta.bulk_group [%0], [%1], %2;"
        :: "l"(gdst), "r"(ssrc), "r"(bytes) : "memory");
}

__global__ __launch_bounds__(TPB)
void radius_graph_kernel(const float* __restrict__ pos,
                         const float* __restrict__ cell,
                         float* __restrict__ out,
                         int B, int N, size_t S)
{
    __shared__ __align__(16) float4 spos4[MAXN];       // 8 KB (xyz + pad)
    __shared__ __align__(16) float4 soff4[KIMG];       // 432 B
    __shared__ __align__(16) float  svec [2][CH * 3];  // 2 x 9 KB
    __shared__ __align__(16) float  sdist[2][CH];      // 2 x 3 KB
    __shared__ __align__(16) float  smask[2][CH];      // 2 x 3 KB

    const int bi = blockIdx.x;        // 0 .. B*N-1
    const int b  = bi / N;
    const int i  = bi - b * N;

    // Load this structure's positions into shared memory as float4
    const float* posb = pos + (size_t)b * N * 3;
    for (int t = threadIdx.x; t < N; t += TPB)
        spos4[t] = make_float4(posb[t * 3 + 0], posb[t * 3 + 1], posb[t * 3 + 2], 0.0f);

    // 27 cartesian image offsets: off[k][d] = sum_c frac[k][c]*cell[b][c][d]
    if (threadIdx.x < KIMG) {
        const int k = threadIdx.x;
        const int f0 = (k / 9) - 1;
        const int f1 = ((k / 3) % 3) - 1;
        const int f2 = (k % 3) - 1;
        const float* cb = cell + b * 9;
        float ox = (float)f0 * cb[0] + (float)f1 * cb[3] + (float)f2 * cb[6];
        float oy = (float)f0 * cb[1] + (float)f1 * cb[4] + (float)f2 * cb[7];
        float oz = (float)f0 * cb[2] + (float)f1 * cb[5] + (float)f2 * cb[8];
        soff4[k] = make_float4(ox, oy, oz, 0.0f);
    }
    __syncthreads();

    const float4 pi4 = spos4[i];
    const float pix = pi4.x, piy = pi4.y, piz = pi4.z;

    float* __restrict__ dist_out = out;
    float* __restrict__ vec_out  = out + S;
    float* __restrict__ mask_out = out + 4 * S;

    const int    NK   = N * KIMG;                 // 13824 = 18 * CH
    const size_t base = (size_t)bi * (size_t)NK;

    uint32_t svec_a[2], sdist_a[2], smask_a[2];
    #pragma unroll
    for (int z = 0; z < 2; z++) {
        svec_a[z]  = (uint32_t)__cvta_generic_to_shared(&svec[z][0]);
        sdist_a[z] = (uint32_t)__cvta_generic_to_shared(&sdist[z][0]);
        smask_a[z] = (uint32_t)__cvta_generic_to_shared(&smask[z][0]);
    }

    int p = 0;
    for (int c = 0; c < NCHUNK; c++) {
        const int c0 = c * CH;

        // Buffer p was handed to the TMA engine 2 iterations ago (one group
        // of 3 bulk stores per iteration); ensure that group has drained.
        if (c >= 2 && threadIdx.x == 0)
            asm volatile("cp.async.bulk.wait_group 1;" ::: "memory");
        __syncthreads();

        // ---- compute: all three outputs -> smem buffers p ----
        float* sv = svec[p];
        float* sd = sdist[p];
        float* sm = smask[p];

        // One division pair per chunk; incremental (j,k) across the unroll.
        const int t0 = c0 + threadIdx.x;
        int j = t0 / KIMG;
        int k = t0 - j * KIMG;

        #pragma unroll
        for (int q = 0; q < CH / TPB; q++) {
            const int lt = threadIdx.x + q * TPB;

            const float4 pj = spos4[j];
            const float4 ok = soff4[k];

            // vec = (pos_j + offset_k) - pos_i  (reference association order)
            const float vx = (pj.x + ok.x) - pix;
            const float vy = (pj.y + ok.y) - piy;
            const float vz = (pj.z + ok.z) - piz;

            const float sq = vx * vx + vy * vy + vz * vz;
            const bool  m  = (sq > 1e-8f) && (sq <= 25.0f);
            const float mf = m ? 1.0f : 0.0f;
            const float dd = m ? sqrtf(sq) : 0.0f;

            sd[lt] = dd;
            sm[lt] = mf;
            // conflict-free smem: bank = (3*lt + c) % 32, gcd(3,32)=1
            sv[lt * 3 + 0] = vx * mf;
            sv[lt * 3 + 1] = vy * mf;
            sv[lt * 3 + 2] = vz * mf;

            // advance t by TPB=256: j += 9, k += 13 (wrap at 27)
            j += JSTEP;
            k += KSTEP;
            if (k >= KIMG) { k -= KIMG; j += 1; }
        }

        // Order generic-proxy STS before async-proxy TMA reads.
        asm volatile("fence.proxy.async.shared::cta;" ::: "memory");
        __syncthreads();

        // ---- drain: three linear bulk bursts per chunk, one commit group ----
        if (threadIdx.x == 0) {
            const size_t idx0 = base + (size_t)c0;
            bulk_s2g(vec_out  + idx0 * 3, svec_a[p],  CH * 3 * 4);
            bulk_s2g(dist_out + idx0,     sdist_a[p], CH * 4);
            bulk_s2g(mask_out + idx0,     smask_a[p], CH * 4);
            asm volatile("cp.async.bulk.commit_group;" ::: "memory");
        }
        p ^= 1;
    }

    // offset_cart tail: the i==0 block of each structure writes 81 floats
    if (i == 0 && threadIdx.x < KIMG) {
        const float4 o4 = soff4[threadIdx.x];
        float* dst = out + 5 * S + (size_t)b * (KIMG * 3) + threadIdx.x * 3;
        dst[0] = o4.x; dst[1] = o4.y; dst[2] = o4.z;
    }

    // Ensure all bulk stores are complete before the block exits.
    if (threadIdx.x == 0)
        asm volatile("cp.async.bulk.wait_group 0;" ::: "memory");
}

extern "C" void kernel_launch(void* const* d_in, const int* in_sizes, int n_in,
                              void* d_out, int out_size)
{
    const float* pos  = (const float*)d_in[0];  // [B, N, 3]
    const float* cell = (const float*)d_in[1];  // [B, 3, 3]

    const int B = in_sizes[1] / 9;              // 4
    const int N = in_sizes[0] / (3 * B);        // 512
    const size_t S = (size_t)B * N * N * KIMG;  // 28,311,552

    float* out = (float*)d_out;

    dim3 grid(B * N);
    dim3 block(TPB);
    radius_graph_kernel<<<grid, block>>>(pos, cell, out, B, N, S);
}

// round 13
// speedup vs baseline: 1.0809x; 1.0809x over previous
#include <cuda_runtime.h>
#include <cuda_bf16.h>
#include <stdint.h>

// Periodic radius-graph: B=4, N=512, K=27.
// Outputs concatenated in d_out (float32):
//   [0,      S)   distances   [B,N,N,K]
//   [S,     4S)   distance_vec[B,N,N,K,3]
//   [4S,    5S)   mask        [B,N,N,K]  (0.0/1.0)
//   [5S, 5S+81B)  offset_cart [B,27,3]
// with S = B*N*N*K.
//
// dist/mask: direct coalesced STG. vec: smem-staged, drained by
// cp.async.bulk shared->global (TMA), double-buffered.
// TPB=512 / CH=1536: halves barrier + chunk overhead vs the 256/768 variant
// while keeping 2048 resident threads/SM (4 blocks x 512).

#define KIMG   27
#define MAXN   512
#define TPB    512
#define CH     1536                // elems/chunk = 3 per thread; NK/CH = 9
#define NCHUNK (MAXN * KIMG / CH)  // 9
// TPB mod KIMG: 512 = 18*27 + 26
#define JSTEP  18
#define KSTEP  26

__device__ __forceinline__ void bulk_s2g(void* gdst, uint32_t ssrc, uint32_t bytes) {
    asm volatile(
        "cp.async.bulk.global.shared::cta.bulk_group [%0], [%1], %2;"
        :: "l"(gdst), "r"(ssrc), "r"(bytes) : "memory");
}

__global__ __launch_bounds__(TPB)
void radius_graph_kernel(const float* __restrict__ pos,
                         const float* __restrict__ cell,
                         float* __restrict__ out,
                         int B, int N, size_t S)
{
    __shared__ __align__(16) float4 spos4[MAXN];      // 8 KB (xyz + pad)
    __shared__ __align__(16) float4 soff4[KIMG];      // 432 B
    __shared__ __align__(16) float  svec[2][CH * 3];  // 2 x 18 KB vec staging

    const int bi = blockIdx.x;        // 0 .. B*N-1
    const int b  = bi / N;
    const int i  = bi - b * N;

    // Load this structure's positions into shared memory as float4
    const float* posb = pos + (size_t)b * N * 3;
    for (int t = threadIdx.x; t < N; t += TPB)
        spos4[t] = make_float4(posb[t * 3 + 0], posb[t * 3 + 1], posb[t * 3 + 2], 0.0f);

    // 27 cartesian image offsets: off[k][d] = sum_c frac[k][c]*cell[b][c][d]
    if (threadIdx.x < KIMG) {
        const int k = threadIdx.x;
        const int f0 = (k / 9) - 1;
        const int f1 = ((k / 3) % 3) - 1;
        const int f2 = (k % 3) - 1;
        const float* cb = cell + b * 9;
        float ox = (float)f0 * cb[0] + (float)f1 * cb[3] + (float)f2 * cb[6];
        float oy = (float)f0 * cb[1] + (float)f1 * cb[4] + (float)f2 * cb[7];
        float oz = (float)f0 * cb[2] + (float)f1 * cb[5] + (float)f2 * cb[8];
        soff4[k] = make_float4(ox, oy, oz, 0.0f);
    }
    __syncthreads();

    const float4 pi4 = spos4[i];
    const float pix = pi4.x, piy = pi4.y, piz = pi4.z;

    float* __restrict__ dist_out = out;
    float* __restrict__ vec_out  = out + S;
    float* __restrict__ mask_out = out + 4 * S;

    const int    NK   = N * KIMG;                 // 13824 = 9 * CH
    const size_t base = (size_t)bi * (size_t)NK;

    uint32_t svec_addr[2];
    svec_addr[0] = (uint32_t)__cvta_generic_to_shared(&svec[0][0]);
    svec_addr[1] = (uint32_t)__cvta_generic_to_shared(&svec[1][0]);

    int p = 0;
    for (int c = 0; c < NCHUNK; c++) {
        const int c0 = c * CH;

        // Buffer p was handed to the TMA engine 2 iterations ago; ensure
        // that bulk-store group has drained before overwriting it.
        if (c >= 2 && threadIdx.x == 0)
            asm volatile("cp.async.bulk.wait_group 1;" ::: "memory");
        __syncthreads();

        // ---- compute: dist/mask direct coalesced, vec -> smem buffer p ----
        float* sv = svec[p];

        // One division pair per chunk; incremental (j,k) across the unroll.
        const int t0 = c0 + threadIdx.x;
        int j = t0 / KIMG;
        int k = t0 - j * KIMG;

        #pragma unroll
        for (int q = 0; q < CH / TPB; q++) {
            const int lt = threadIdx.x + q * TPB;
            const int t  = c0 + lt;

            const float4 pj = spos4[j];
            const float4 ok = soff4[k];

            // vec = (pos_j + offset_k) - pos_i  (reference association order)
            const float vx = (pj.x + ok.x) - pix;
            const float vy = (pj.y + ok.y) - piy;
            const float vz = (pj.z + ok.z) - piz;

            const float sq = vx * vx + vy * vy + vz * vz;
            const bool  m  = (sq > 1e-8f) && (sq <= 25.0f);
            const float mf = m ? 1.0f : 0.0f;
            const float dd = m ? sqrtf(sq) : 0.0f;

            const size_t idx = base + (size_t)t;
            dist_out[idx] = dd;
            mask_out[idx] = mf;
            // conflict-free smem: bank = (3*lt + c) % 32, gcd(3,32)=1
            sv[lt * 3 + 0] = vx * mf;
            sv[lt * 3 + 1] = vy * mf;
            sv[lt * 3 + 2] = vz * mf;

            // advance t by TPB=512: j += 18, k += 26 (wrap at 27)
            j += JSTEP;
            k += KSTEP;
            if (k >= KIMG) { k -= KIMG; j += 1; }
        }

        // Order generic-proxy STS before async-proxy TMA read.
        asm volatile("fence.proxy.async.shared::cta;" ::: "memory");
        __syncthreads();

        // ---- drain: one thread hands the 18432-B chunk to the TMA engine ----
        if (threadIdx.x == 0) {
            bulk_s2g(vec_out + (base + (size_t)c0) * 3, svec_addr[p], CH * 3 * 4);
            asm volatile("cp.async.bulk.commit_group;" ::: "memory");
        }
        p ^= 1;
    }

    // offset_cart tail: the i==0 block of each structure writes 81 floats
    if (i == 0 && threadIdx.x < KIMG) {
        const float4 o4 = soff4[threadIdx.x];
        float* dst = out + 5 * S + (size_t)b * (KIMG * 3) + threadIdx.x * 3;
        dst[0] = o4.x; dst[1] = o4.y; dst[2] = o4.z;
    }

    // Ensure all bulk stores are complete before the block exits.
    if (threadIdx.x == 0)
        asm volatile("cp.async.bulk.wait_group 0;" ::: "memory");
}

extern "C" void kernel_launch(void* const* d_in, const int* in_sizes, int n_in,
                              void* d_out, int out_size)
{
    const float* pos  = (const float*)d_in[0];  // [B, N, 3]
    const float* cell = (const float*)d_in[1];  // [B, 3, 3]

    const int B = in_sizes[1] / 9;              // 4
    const int N = in_sizes[0] / (3 * B);        // 512
    const size_t S = (size_t)B * N * N * KIMG;  // 28,311,552

    float* out = (float*)d_out;

    dim3 grid(B * N);
    dim3 block(TPB);
    radius_graph_kernel<<<grid, block>>>(pos, cell, out, B, N, S);
}

// round 14
// speedup vs baseline: 1.1545x; 1.0680x over previous
#include <cuda_runtime.h>
#include <cuda_bf16.h>
#include <stdint.h>

// Periodic radius-graph: B=4, N=512, K=27.
// Outputs concatenated in d_out (float32):
//   [0,      S)   distances   [B,N,N,K]
//   [S,     4S)   distance_vec[B,N,N,K,3]
//   [4S,    5S)   mask        [B,N,N,K]  (0.0/1.0)
//   [5S, 5S+81B)  offset_cart [B,27,3]
// with S = B*N*N*K.
//
// dist/mask: direct coalesced STG. vec: smem-staged, drained by
// cp.async.bulk shared->global (TMA), double-buffered.
// TPB=1024 / CH=3456 / NCHUNK=4: 8 barriers per block (vs 18), 41.5 KB TMA
// bursts, 2 blocks x 1024 = 2048 resident threads/SM. Dynamic smem (91.6 KB).

#define KIMG   27
#define MAXN   512
#define TPB    1024
#define CH     3456                // NK/4; per thread: 3 full + partial(384)
#define NCHUNK 4
// TPB mod KIMG: 1024 = 37*27 + 25
#define JSTEP  37
#define KSTEP  25

// dynamic smem layout (bytes):
//   [0,     8192)   spos4[512]  (float4)
//   [8192,  8704)   soff4[32]   (float4, 27 used)
//   [8704, 91648)   svec[2][CH*3] (float)
#define SMEM_SPOS  0
#define SMEM_SOFF  8192
#define SMEM_SVEC  8704
#define SMEM_BYTES (SMEM_SVEC + 2 * CH * 3 * 4)   // 91648

__device__ __forceinline__ void bulk_s2g(void* gdst, uint32_t ssrc, uint32_t bytes) {
    asm volatile(
        "cp.async.bulk.global.shared::cta.bulk_group [%0], [%1], %2;"
        :: "l"(gdst), "r"(ssrc), "r"(bytes) : "memory");
}

__global__ __launch_bounds__(TPB)
void radius_graph_kernel(const float* __restrict__ pos,
                         const float* __restrict__ cell,
                         float* __restrict__ out,
                         int B, int N, size_t S)
{
    extern __shared__ __align__(16) char smem[];
    float4* spos4 = (float4*)(smem + SMEM_SPOS);
    float4* soff4 = (float4*)(smem + SMEM_SOFF);
    float*  svec0 = (float*)(smem + SMEM_SVEC);

    const int bi = blockIdx.x;        // 0 .. B*N-1
    const int b  = bi / N;
    const int i  = bi - b * N;

    // Load this structure's positions into shared memory as float4
    const float* posb = pos + (size_t)b * N * 3;
    for (int t = threadIdx.x; t < N; t += TPB)
        spos4[t] = make_float4(posb[t * 3 + 0], posb[t * 3 + 1], posb[t * 3 + 2], 0.0f);

    // 27 cartesian image offsets: off[k][d] = sum_c frac[k][c]*cell[b][c][d]
    if (threadIdx.x < KIMG) {
        const int k = threadIdx.x;
        const int f0 = (k / 9) - 1;
        const int f1 = ((k / 3) % 3) - 1;
        const int f2 = (k % 3) - 1;
        const float* cb = cell + b * 9;
        float ox = (float)f0 * cb[0] + (float)f1 * cb[3] + (float)f2 * cb[6];
        float oy = (float)f0 * cb[1] + (float)f1 * cb[4] + (float)f2 * cb[7];
        float oz = (float)f0 * cb[2] + (float)f1 * cb[5] + (float)f2 * cb[8];
        soff4[k] = make_float4(ox, oy, oz, 0.0f);
    }
    __syncthreads();

    const float4 pi4 = spos4[i];
    const float pix = pi4.x, piy = pi4.y, piz = pi4.z;

    float* __restrict__ dist_out = out;
    float* __restrict__ vec_out  = out + S;
    float* __restrict__ mask_out = out + 4 * S;

    const int    NK   = N * KIMG;                 // 13824 = 4 * CH
    const size_t base = (size_t)bi * (size_t)NK;

    uint32_t svec_addr[2];
    svec_addr[0] = (uint32_t)__cvta_generic_to_shared(svec0);
    svec_addr[1] = (uint32_t)__cvta_generic_to_shared(svec0 + CH * 3);

    int p = 0;
    for (int c = 0; c < NCHUNK; c++) {
        const int c0 = c * CH;

        // Buffer p was handed to the TMA engine 2 iterations ago; ensure
        // that bulk-store group has drained before overwriting it.
        if (c >= 2 && threadIdx.x == 0)
            asm volatile("cp.async.bulk.wait_group 1;" ::: "memory");
        __syncthreads();

        // ---- compute: dist/mask direct coalesced, vec -> smem buffer p ----
        float* sv = svec0 + p * (CH * 3);

        // One division pair per chunk; incremental (j,k) across the unroll.
        const int t0 = c0 + threadIdx.x;
        int j = t0 / KIMG;
        int k = t0 - j * KIMG;

        #pragma unroll
        for (int q = 0; q < (CH + TPB - 1) / TPB; q++) {   // 3 full + 1 partial
            const int lt = threadIdx.x + q * TPB;
            if (lt < CH) {
                const int t = c0 + lt;

                const float4 pj = spos4[j];
                const float4 ok = soff4[k];

                // vec = (pos_j + offset_k) - pos_i  (reference association order)
                const float vx = (pj.x + ok.x) - pix;
                const float vy = (pj.y + ok.y) - piy;
                const float vz = (pj.z + ok.z) - piz;

                const float sq = vx * vx + vy * vy + vz * vz;
                const bool  m  = (sq > 1e-8f) && (sq <= 25.0f);
                const float mf = m ? 1.0f : 0.0f;
                const float dd = m ? sqrtf(sq) : 0.0f;

                const size_t idx = base + (size_t)t;
                dist_out[idx] = dd;
                mask_out[idx] = mf;
                // conflict-free smem: bank = (3*lt + c) % 32, gcd(3,32)=1
                sv[lt * 3 + 0] = vx * mf;
                sv[lt * 3 + 1] = vy * mf;
                sv[lt * 3 + 2] = vz * mf;
            }
            // advance t by TPB=1024: j += 37, k += 25 (wrap at 27)
            j += JSTEP;
            k += KSTEP;
            if (k >= KIMG) { k -= KIMG; j += 1; }
        }

        // Order generic-proxy STS before async-proxy TMA read.
        asm volatile("fence.proxy.async.shared::cta;" ::: "memory");
        __syncthreads();

        // ---- drain: one thread hands the 41472-B chunk to the TMA engine ----
        if (threadIdx.x == 0) {
            bulk_s2g(vec_out + (base + (size_t)c0) * 3, svec_addr[p], CH * 3 * 4);
            asm volatile("cp.async.bulk.commit_group;" ::: "memory");
        }
        p ^= 1;
    }

    // offset_cart tail: the i==0 block of each structure writes 81 floats
    if (i == 0 && threadIdx.x < KIMG) {
        const float4 o4 = soff4[threadIdx.x];
        float* dst = out + 5 * S + (size_t)b * (KIMG * 3) + threadIdx.x * 3;
        dst[0] = o4.x; dst[1] = o4.y; dst[2] = o4.z;
    }

    // Ensure all bulk stores are complete before the block exits.
    if (threadIdx.x == 0)
        asm volatile("cp.async.bulk.wait_group 0;" ::: "memory");
}

extern "C" void kernel_launch(void* const* d_in, const int* in_sizes, int n_in,
                              void* d_out, int out_size)
{
    const float* pos  = (const float*)d_in[0];  // [B, N, 3]
    const float* cell = (const float*)d_in[1];  // [B, 3, 3]

    const int B = in_sizes[1] / 9;              // 4
    const int N = in_sizes[0] / (3 * B);        // 512
    const size_t S = (size_t)B * N * N * KIMG;  // 28,311,552

    float* out = (float*)d_out;

    // Opt in to >48KB dynamic smem (host attribute, not a stream op).
    cudaFuncSetAttribute(radius_graph_kernel,
                         cudaFuncAttributeMaxDynamicSharedMemorySize, SMEM_BYTES);

    dim3 grid(B * N);
    dim3 block(TPB);
    radius_graph_kernel<<<grid, block, SMEM_BYTES>>>(pos, cell, out, B, N, S);
}

// round 15
// speedup vs baseline: 1.1650x; 1.0091x over previous
#include <cuda_runtime.h>
#include <cuda_bf16.h>
#include <stdint.h>

// Periodic radius-graph: B=4, N=512, K=27.
// Outputs concatenated in d_out (float32):
//   [0,      S)   distances   [B,N,N,K]
//   [S,     4S)   distance_vec[B,N,N,K,3]
//   [4S,    5S)   mask        [B,N,N,K]  (0.0/1.0)
//   [5S, 5S+81B)  offset_cart [B,27,3]
// with S = B*N*N*K.
//
// dist/mask: direct coalesced STG. vec: smem-staged, drained by
// cp.async.bulk shared->global (TMA), double-buffered.
// TPB=1024 / CH=3456 / NCHUNK=4. soff stored SoA (scalar, conflict-free
// LDS.32) since k is the warp-fast index; spos stays float4 (broadcast).

#define KIMG   27
#define MAXN   512
#define TPB    1024
#define CH     3456                // NK/4; per thread: 3 full + partial(384)
#define NCHUNK 4
// TPB mod KIMG: 1024 = 37*27 + 25
#define JSTEP  37
#define KSTEP  25

// dynamic smem layout (bytes):
//   [0,     8192)   spos4[512]   (float4)
//   [8192,  8320)   soffx[32]    (float)
//   [8320,  8448)   soffy[32]    (float)
//   [8448,  8576)   soffz[32]    (float)
//   [8576, 91520)   svec[2][CH*3] (float)
#define SMEM_SPOS  0
#define SMEM_SOFFX 8192
#define SMEM_SOFFY 8320
#define SMEM_SOFFZ 8448
#define SMEM_SVEC  8576
#define SMEM_BYTES (SMEM_SVEC + 2 * CH * 3 * 4)   // 91520

__device__ __forceinline__ void bulk_s2g(void* gdst, uint32_t ssrc, uint32_t bytes) {
    asm volatile(
        "cp.async.bulk.global.shared::cta.bulk_group [%0], [%1], %2;"
        :: "l"(gdst), "r"(ssrc), "r"(bytes) : "memory");
}

__global__ __launch_bounds__(TPB)
void radius_graph_kernel(const float* __restrict__ pos,
                         const float* __restrict__ cell,
                         float* __restrict__ out,
                         int B, int N, size_t S)
{
    extern __shared__ __align__(16) char smem[];
    float4* spos4 = (float4*)(smem + SMEM_SPOS);
    float*  soffx = (float*)(smem + SMEM_SOFFX);
    float*  soffy = (float*)(smem + SMEM_SOFFY);
    float*  soffz = (float*)(smem + SMEM_SOFFZ);
    float*  svec0 = (float*)(smem + SMEM_SVEC);

    const int bi = blockIdx.x;        // 0 .. B*N-1
    const int b  = bi / N;
    const int i  = bi - b * N;

    // Load this structure's positions into shared memory as float4
    const float* posb = pos + (size_t)b * N * 3;
    for (int t = threadIdx.x; t < N; t += TPB)
        spos4[t] = make_float4(posb[t * 3 + 0], posb[t * 3 + 1], posb[t * 3 + 2], 0.0f);

    // 27 cartesian image offsets: off[k][d] = sum_c frac[k][c]*cell[b][c][d]
    if (threadIdx.x < KIMG) {
        const int k = threadIdx.x;
        const int f0 = (k / 9) - 1;
        const int f1 = ((k / 3) % 3) - 1;
        const int f2 = (k % 3) - 1;
        const float* cb = cell + b * 9;
        soffx[k] = (float)f0 * cb[0] + (float)f1 * cb[3] + (float)f2 * cb[6];
        soffy[k] = (float)f0 * cb[1] + (float)f1 * cb[4] + (float)f2 * cb[7];
        soffz[k] = (float)f0 * cb[2] + (float)f1 * cb[5] + (float)f2 * cb[8];
    }
    __syncthreads();

    const float4 pi4 = spos4[i];
    const float pix = pi4.x, piy = pi4.y, piz = pi4.z;

    float* __restrict__ dist_out = out;
    float* __restrict__ vec_out  = out + S;
    float* __restrict__ mask_out = out + 4 * S;

    const int    NK   = N * KIMG;                 // 13824 = 4 * CH
    const size_t base = (size_t)bi * (size_t)NK;

    uint32_t svec_addr[2];
    svec_addr[0] = (uint32_t)__cvta_generic_to_shared(svec0);
    svec_addr[1] = (uint32_t)__cvta_generic_to_shared(svec0 + CH * 3);

    int p = 0;
    for (int c = 0; c < NCHUNK; c++) {
        const int c0 = c * CH;

        // Buffer p was handed to the TMA engine 2 iterations ago; ensure
        // that bulk-store group has drained before overwriting it.
        if (c >= 2 && threadIdx.x == 0)
            asm volatile("cp.async.bulk.wait_group 1;" ::: "memory");
        __syncthreads();

        // ---- compute: dist/mask direct coalesced, vec -> smem buffer p ----
        float* sv = svec0 + p * (CH * 3);

        // One division pair per chunk; incremental (j,k) across the unroll.
        const int t0 = c0 + threadIdx.x;
        int j = t0 / KIMG;
        int k = t0 - j * KIMG;

        #pragma unroll
        for (int q = 0; q < (CH + TPB - 1) / TPB; q++) {   // 3 full + 1 partial
            const int lt = threadIdx.x + q * TPB;
            if (lt < CH) {
                const int t = c0 + lt;

                const float4 pj = spos4[j];      // near-broadcast (LDS.128)
                const float okx = soffx[k];      // conflict-free LDS.32
                const float oky = soffy[k];
                const float okz = soffz[k];

                // vec = (pos_j + offset_k) - pos_i  (reference association order)
                const float vx = (pj.x + okx) - pix;
                const float vy = (pj.y + oky) - piy;
                const float vz = (pj.z + okz) - piz;

                const float sq = vx * vx + vy * vy + vz * vz;
                const bool  m  = (sq > 1e-8f) && (sq <= 25.0f);
                const float mf = m ? 1.0f : 0.0f;
                const float dd = m ? sqrtf(sq) : 0.0f;

                const size_t idx = base + (size_t)t;
                dist_out[idx] = dd;
                mask_out[idx] = mf;
                // conflict-free smem: bank = (3*lt + c) % 32, gcd(3,32)=1
                sv[lt * 3 + 0] = vx * mf;
                sv[lt * 3 + 1] = vy * mf;
                sv[lt * 3 + 2] = vz * mf;
            }
            // advance t by TPB=1024: j += 37, k += 25 (wrap at 27)
            j += JSTEP;
            k += KSTEP;
            if (k >= KIMG) { k -= KIMG; j += 1; }
        }

        // Order generic-proxy STS before async-proxy TMA read.
        asm volatile("fence.proxy.async.shared::cta;" ::: "memory");
        __syncthreads();

        // ---- drain: one thread hands the 41472-B chunk to the TMA engine ----
        if (threadIdx.x == 0) {
            bulk_s2g(vec_out + (base + (size_t)c0) * 3, svec_addr[p], CH * 3 * 4);
            asm volatile("cp.async.bulk.commit_group;" ::: "memory");
        }
        p ^= 1;
    }

    // offset_cart tail: the i==0 block of each structure writes 81 floats
    if (i == 0 && threadIdx.x < KIMG) {
        const int k = threadIdx.x;
        float* dst = out + 5 * S + (size_t)b * (KIMG * 3) + k * 3;
        dst[0] = soffx[k]; dst[1] = soffy[k]; dst[2] = soffz[k];
    }

    // Ensure all bulk stores are complete before the block exits.
    if (threadIdx.x == 0)
        asm volatile("cp.async.bulk.wait_group 0;" ::: "memory");
}

extern "C" void kernel_launch(void* const* d_in, const int* in_sizes, int n_in,
                              void* d_out, int out_size)
{
    const float* pos  = (const float*)d_in[0];  // [B, N, 3]
    const float* cell = (const float*)d_in[1];  // [B, 3, 3]

    const int B = in_sizes[1] / 9;              // 4
    const int N = in_sizes[0] / (3 * B);        // 512
    const size_t S = (size_t)B * N * N * KIMG;  // 28,311,552

    float* out = (float*)d_out;

    // Opt in to >48KB dynamic smem (host attribute, not a stream op).
    cudaFuncSetAttribute(radius_graph_kernel,
                         cudaFuncAttributeMaxDynamicSharedMemorySize, SMEM_BYTES);

    dim3 grid(B * N);
    dim3 block(TPB);
    radius_graph_kernel<<<grid, block, SMEM_BYTES>>>(pos, cell, out, B, N, S);
}

// round 16
// speedup vs baseline: 1.1685x; 1.0030x over previous
#include <cuda_runtime.h>
#include <cuda_bf16.h>
#include <stdint.h>

// Periodic radius-graph: B=4, N=512, K=27.
// Outputs concatenated in d_out (float32):
//   [0,      S)   distances   [B,N,N,K]
//   [S,     4S)   distance_vec[B,N,N,K,3]
//   [4S,    5S)   mask        [B,N,N,K]  (0.0/1.0)
//   [5S, 5S+81B)  offset_cart [B,27,3]
// with S = B*N*N*K.
//
// dist/mask: direct coalesced STG. vec: smem-staged, drained by
// cp.async.bulk shared->global (TMA), double-buffered.
// TPB=864 = 32*27: k = tid%27 is a kernel-lifetime constant, so the three
// soff reads hoist out of the loop and j is pure incremental addition.
// CH=3456 (4 elems/thread, all iterations full-width), NCHUNK=4.

#define KIMG   27
#define MAXN   512
#define TPB    864                 // 32 * 27
#define CH     3456                // 4 * TPB; NK/CH = 4
#define NCHUNK 4
#define JQ     (TPB / KIMG)        // 32: j-advance per q step
#define JC     (CH / KIMG)         // 128: j-advance per chunk

// dynamic smem layout (bytes):
//   [0,     8192)   spos4[512]   (float4)
//   [8192,  8320)   soffx[32]    (float)
//   [8320,  8448)   soffy[32]    (float)
//   [8448,  8576)   soffz[32]    (float)
//   [8576, 91520)   svec[2][CH*3] (float)
#define SMEM_SPOS  0
#define SMEM_SOFFX 8192
#define SMEM_SOFFY 8320
#define SMEM_SOFFZ 8448
#define SMEM_SVEC  8576
#define SMEM_BYTES (SMEM_SVEC + 2 * CH * 3 * 4)   // 91520

__device__ __forceinline__ void bulk_s2g(void* gdst, uint32_t ssrc, uint32_t bytes) {
    asm volatile(
        "cp.async.bulk.global.shared::cta.bulk_group [%0], [%1], %2;"
        :: "l"(gdst), "r"(ssrc), "r"(bytes) : "memory");
}

__global__ __launch_bounds__(TPB)
void radius_graph_kernel(const float* __restrict__ pos,
                         const float* __restrict__ cell,
                         float* __restrict__ out,
                         int B, int N, size_t S)
{
    extern __shared__ __align__(16) char smem[];
    float4* spos4 = (float4*)(smem + SMEM_SPOS);
    float*  soffx = (float*)(smem + SMEM_SOFFX);
    float*  soffy = (float*)(smem + SMEM_SOFFY);
    float*  soffz = (float*)(smem + SMEM_SOFFZ);
    float*  svec0 = (float*)(smem + SMEM_SVEC);

    const int bi = blockIdx.x;        // 0 .. B*N-1
    const int b  = bi / N;
    const int i  = bi - b * N;

    // Load this structure's positions into shared memory as float4
    const float* posb = pos + (size_t)b * N * 3;
    for (int t = threadIdx.x; t < N; t += TPB)
        spos4[t] = make_float4(posb[t * 3 + 0], posb[t * 3 + 1], posb[t * 3 + 2], 0.0f);

    // 27 cartesian image offsets: off[k][d] = sum_c frac[k][c]*cell[b][c][d]
    if (threadIdx.x < KIMG) {
        const int k = threadIdx.x;
        const int f0 = (k / 9) - 1;
        const int f1 = ((k / 3) % 3) - 1;
        const int f2 = (k % 3) - 1;
        const float* cb = cell + b * 9;
        soffx[k] = (float)f0 * cb[0] + (float)f1 * cb[3] + (float)f2 * cb[6];
        soffy[k] = (float)f0 * cb[1] + (float)f1 * cb[4] + (float)f2 * cb[7];
        soffz[k] = (float)f0 * cb[2] + (float)f1 * cb[5] + (float)f2 * cb[8];
    }
    __syncthreads();

    const float4 pi4 = spos4[i];
    const float pix = pi4.x, piy = pi4.y, piz = pi4.z;

    // k is a kernel-lifetime constant per thread; soff reads hoisted here.
    const int j0 = threadIdx.x / KIMG;              // 0..31
    const int kk = threadIdx.x - j0 * KIMG;         // 0..26
    const float okx = soffx[kk];
    const float oky = soffy[kk];
    const float okz = soffz[kk];

    float* __restrict__ dist_out = out;
    float* __restrict__ vec_out  = out + S;
    float* __restrict__ mask_out = out + 4 * S;

    const int    NK   = N * KIMG;                 // 13824 = 4 * CH
    const size_t base = (size_t)bi * (size_t)NK;

    uint32_t svec_addr[2];
    svec_addr[0] = (uint32_t)__cvta_generic_to_shared(svec0);
    svec_addr[1] = (uint32_t)__cvta_generic_to_shared(svec0 + CH * 3);

    int p = 0;
    for (int c = 0; c < NCHUNK; c++) {
        const int c0 = c * CH;

        // Buffer p was handed to the TMA engine 2 iterations ago; ensure
        // that bulk-store group has drained before overwriting it.
        if (c >= 2 && threadIdx.x == 0)
            asm volatile("cp.async.bulk.wait_group 1;" ::: "memory");
        __syncthreads();

        // ---- compute: dist/mask direct coalesced, vec -> smem buffer p ----
        float* sv = svec0 + p * (CH * 3);

        int j = c * JC + j0;                       // j advances by 32 per q

        #pragma unroll
        for (int q = 0; q < NCHUNK; q++) {         // 4 full-width iterations
            const int lt = threadIdx.x + q * TPB;
            const int t  = c0 + lt;

            const float4 pj = spos4[j];            // near-broadcast LDS.128

            // vec = (pos_j + offset_k) - pos_i  (reference association order)
            const float vx = (pj.x + okx) - pix;
            const float vy = (pj.y + oky) - piy;
            const float vz = (pj.z + okz) - piz;

            const float sq = vx * vx + vy * vy + vz * vz;
            const bool  m  = (sq > 1e-8f) && (sq <= 25.0f);
            const float mf = m ? 1.0f : 0.0f;
            const float dd = m ? sqrtf(sq) : 0.0f;

            const size_t idx = base + (size_t)t;
            dist_out[idx] = dd;
            mask_out[idx] = mf;
            // conflict-free smem: bank = (3*lt + c) % 32, gcd(3,32)=1
            sv[lt * 3 + 0] = vx * mf;
            sv[lt * 3 + 1] = vy * mf;
            sv[lt * 3 + 2] = vz * mf;

            j += JQ;
        }

        // Order generic-proxy STS before async-proxy TMA read.
        asm volatile("fence.proxy.async.shared::cta;" ::: "memory");
        __syncthreads();

        // ---- drain: one thread hands the 41472-B chunk to the TMA engine ----
        if (threadIdx.x == 0) {
            bulk_s2g(vec_out + (base + (size_t)c0) * 3, svec_addr[p], CH * 3 * 4);
            asm volatile("cp.async.bulk.commit_group;" ::: "memory");
        }
        p ^= 1;
    }

    // offset_cart tail: the i==0 block of each structure writes 81 floats
    if (i == 0 && threadIdx.x < KIMG) {
        const int k = threadIdx.x;
        float* dst = out + 5 * S + (size_t)b * (KIMG * 3) + k * 3;
        dst[0] = soffx[k]; dst[1] = soffy[k]; dst[2] = soffz[k];
    }

    // Ensure all bulk stores are complete before the block exits.
    if (threadIdx.x == 0)
        asm volatile("cp.async.bulk.wait_group 0;" ::: "memory");
}

extern "C" void kernel_launch(void* const* d_in, const int* in_sizes, int n_in,
                              void* d_out, int out_size)
{
    const float* pos  = (const float*)d_in[0];  // [B, N, 3]
    const float* cell = (const float*)d_in[1];  // [B, 3, 3]

    const int B = in_sizes[1] / 9;              // 4
    const int N = in_sizes[0] / (3 * B);        // 512
    const size_t S = (size_t)B * N * N * KIMG;  // 28,311,552

    float* out = (float*)d_out;

    // Opt in to >48KB dynamic smem (host attribute, not a stream op).
    cudaFuncSetAttribute(radius_graph_kernel,
                         cudaFuncAttributeMaxDynamicSharedMemorySize, SMEM_BYTES);

    dim3 grid(B * N);
    dim3 block(TPB);
    radius_graph_kernel<<<grid, block, SMEM_BYTES>>>(pos, cell, out, B, N, S);
}